// round 14
// baseline (speedup 1.0000x reference)
#include <cuda_runtime.h>
#include <cuda_fp16.h>
#include <math.h>
#include <stdint.h>

#define BB 8
#define SS 1024
#define EE 512
#define NH 8
#define NQ 16
#define FFN 2048
#define NL 4
#define TT (BB*SS)   // 8192 tokens

// ---------------- scratch (static device globals; no allocation) -------------
__device__ float g_h[TT*EE];                 // 16 MB  current hidden state
__device__ float g_attn[TT*NQ];              // 0.5 MB attention output
__device__ __half g_w2h[(size_t)NL*EE*FFN];  // 8 MB   W2 in fp16
__device__ __half g_w1h[(size_t)NL*FFN*NQ];  // 256 KB W1 in fp16

// ---------------- PTX helpers -------------------------------------------------
__device__ __forceinline__ float ex2f(float x) {
    float r; asm("ex2.approx.f32 %0, %1;" : "=f"(r) : "f"(x)); return r;
}
__device__ __forceinline__ uint32_t smem_u32(const void* p) {
    uint32_t a;
    asm("{ .reg .u64 t; cvta.to.shared.u64 t, %1; cvt.u32.u64 %0, t; }" : "=r"(a) : "l"(p));
    return a;
}
__device__ __forceinline__ uint32_t pack_h2(float a, float b) {
    __half2 h = __floats2half2_rn(a, b);
    return *(uint32_t*)&h;
}
__device__ __forceinline__ void cp16(uint32_t dst, const void* src) {
    asm volatile("cp.async.cg.shared.global [%0], [%1], 16;" :: "r"(dst), "l"(src) : "memory");
}
#define CP_COMMIT() asm volatile("cp.async.commit_group;" ::: "memory")
#define CP_WAIT0()  asm volatile("cp.async.wait_group 0;" ::: "memory")

__device__ __forceinline__ void ldsm4(uint32_t* r, uint32_t a) {
    asm volatile("ldmatrix.sync.aligned.m8n8.x4.shared.b16 {%0,%1,%2,%3}, [%4];"
                 : "=r"(r[0]), "=r"(r[1]), "=r"(r[2]), "=r"(r[3]) : "r"(a));
}
// fp16 mma, fp32 accumulate
__device__ __forceinline__ void mma_f16(float* c, const uint32_t* a, uint32_t b0, uint32_t b1) {
    asm volatile("mma.sync.aligned.m16n8k16.row.col.f32.f16.f16.f32 "
                 "{%0,%1,%2,%3}, {%4,%5,%6,%7}, {%8,%9}, {%0,%1,%2,%3};"
                 : "+f"(c[0]), "+f"(c[1]), "+f"(c[2]), "+f"(c[3])
                 : "r"(a[0]), "r"(a[1]), "r"(a[2]), "r"(a[3]), "r"(b0), "r"(b1));
}

// ---------------- K0: h = x + pe ---------------------------------------------
__global__ void k_addpe(const float* __restrict__ x, const float* __restrict__ pe) {
    int i = blockIdx.x * 256 + threadIdx.x;
    float4 xv = ((const float4*)x)[i];
    float4 pv = ((const float4*)pe)[i % (SS*EE/4)];
    float4 o; o.x = xv.x+pv.x; o.y = xv.y+pv.y; o.z = xv.z+pv.z; o.w = xv.w+pv.w;
    ((float4*)g_h)[i] = o;
}

// ---------------- Kcvt: W2/W1 -> fp16 copies ---------------------------------
__global__ void k_cvtw2(const float* __restrict__ w2) {
    size_t i = (size_t)blockIdx.x * 256 + threadIdx.x;
    float4 v = ((const float4*)w2)[i];
    ((uint32_t*)g_w2h)[2*i]   = pack_h2(v.x, v.y);
    ((uint32_t*)g_w2h)[2*i+1] = pack_h2(v.z, v.w);
}
__global__ void k_cvtw1(const float* __restrict__ w1) {
    size_t i = (size_t)blockIdx.x * 256 + threadIdx.x;
    float4 v = ((const float4*)w1)[i];
    ((uint32_t*)g_w1h)[2*i]   = pack_h2(v.x, v.y);
    ((uint32_t*)g_w1h)[2*i+1] = pack_h2(v.z, v.w);
}

// ---------------- KA: quantum attention, 2-way key split ---------------------
// block 512 thr: 256 queries x 2 key-halves. grid (4, NH, BB).
__global__ void __launch_bounds__(512) k_attn(const float* __restrict__ theta, int l) {
    __shared__ float2 sk[SS];
    __shared__ float4 pp[256];
    int b = blockIdx.z, hh = blockIdx.y, qc = blockIdx.x;
    float ct0 = cosf(theta[l*NQ + 2*hh]);
    float ct1 = cosf(theta[l*NQ + 2*hh + 1]);
    for (int k = threadIdx.x; k < SS; k += 512) {
        const float* hp = &g_h[((size_t)b*SS + k)*EE + 2*hh];
        sk[k] = make_float2(ct0 * cosf(hp[0]), ct1 * cosf(hp[1]));
    }
    __syncthreads();
    int qi = threadIdx.x & 255;
    int half = threadIdx.x >> 8;
    int q = qc*256 + qi;
    float2 qv = sk[q];
    const float SC = 0.7071067811865476f * 1.4426950408889634f;
    float qm0 = qv.x * SC, qm1 = qv.y * SC;
    float sum = 0.f, a0 = 0.f, a1 = 0.f;
    int k0 = half * 512;
    #pragma unroll 4
    for (int k = k0; k < k0 + 512; k++) {
        float2 kv = sk[k];
        float f = fmaf(qm0, kv.x, qm1 * kv.y);
        float e = ex2f(f);
        sum += e;
        a0 = fmaf(e, kv.x, a0);
        a1 = fmaf(e, kv.y, a1);
    }
    if (half == 1) pp[qi] = make_float4(sum, a0, a1, 0.f);
    __syncthreads();
    if (half == 0) {
        float4 o = pp[qi];
        sum += o.x; a0 += o.y; a1 += o.z;
        float inv = __frcp_rn(sum);
        float* op = &g_attn[((size_t)b*SS + q)*NQ + 2*hh];
        op[0] = a0 * inv;
        op[1] = a1 * inv;
    }
}

// ---------------- KB: attn @ Wc^T + residual + LN1 (warp-per-token) ----------
__global__ void __launch_bounds__(256) k_comb_ln(const float* __restrict__ Wc,
                          const float* __restrict__ g1, const float* __restrict__ b1,
                          int l) {
    __shared__ __align__(16) float wcs[NQ*EE];
    __shared__ float sat[32*NQ];
    int t0 = blockIdx.x * 32;
    const float* W = Wc + (size_t)l*EE*NQ;
    for (int idx = threadIdx.x; idx < EE*NQ; idx += 256) {
        int e = idx >> 4, i = idx & 15;
        wcs[i*EE + e] = W[idx];
    }
    for (int idx = threadIdx.x; idx < 32*NQ; idx += 256)
        sat[idx] = g_attn[(size_t)t0*NQ + idx];
    __syncthreads();

    int w = threadIdx.x >> 5, ln = threadIdx.x & 31;
    int eb = ln * 4;
    for (int tt = 0; tt < 4; tt++) {
        int tl = w*4 + tt;
        size_t t = t0 + tl;
        float v[16];
        #pragma unroll
        for (int j = 0; j < 4; j++) {
            float4 hv = *(const float4*)&g_h[t*EE + eb + j*128];
            v[j*4+0] = hv.x; v[j*4+1] = hv.y; v[j*4+2] = hv.z; v[j*4+3] = hv.w;
        }
        #pragma unroll
        for (int i = 0; i < NQ; i++) {
            float ai = sat[tl*NQ + i];
            const float4* wp = (const float4*)&wcs[i*EE + eb];
            #pragma unroll
            for (int j = 0; j < 4; j++) {
                float4 wv = wp[32*j];
                v[j*4+0] = fmaf(ai, wv.x, v[j*4+0]);
                v[j*4+1] = fmaf(ai, wv.y, v[j*4+1]);
                v[j*4+2] = fmaf(ai, wv.z, v[j*4+2]);
                v[j*4+3] = fmaf(ai, wv.w, v[j*4+3]);
            }
        }
        float s1 = 0.f, s2 = 0.f;
        #pragma unroll
        for (int j = 0; j < 16; j++) { s1 += v[j]; s2 = fmaf(v[j], v[j], s2); }
        #pragma unroll
        for (int o = 16; o > 0; o >>= 1) {
            s1 += __shfl_xor_sync(0xffffffffu, s1, o);
            s2 += __shfl_xor_sync(0xffffffffu, s2, o);
        }
        float m  = s1 * (1.f/512.f);
        float var = fmaf(-m, m, s2 * (1.f/512.f));
        float rs = rsqrtf(var + 1e-5f);
        #pragma unroll
        for (int j = 0; j < 4; j++) {
            float4 gv = *(const float4*)&g1[l*EE + eb + j*128];
            float4 bv = *(const float4*)&b1[l*EE + eb + j*128];
            float4 o4;
            o4.x = (v[j*4+0]-m)*rs*gv.x + bv.x;
            o4.y = (v[j*4+1]-m)*rs*gv.y + bv.y;
            o4.z = (v[j*4+2]-m)*rs*gv.z + bv.z;
            o4.w = (v[j*4+3]-m)*rs*gv.w + bv.w;
            *(float4*)&g_h[t*EE + eb + j*128] = o4;
        }
    }
}

// ---------------- KF: fused FFN (fp16 mma): relu(qf@W1^T)@W2^T + res + LN2 ---
// CTA: M=64 tokens x N=512 (full E). K-tile 64 halfs (128B rows), 32 stages,
// 2-stage cp.async. 512 threads = 16 warps; main warp tile 32x64.
// A tile generated per stage: 1 fp16 gen-mma per (16tok x 8col) tile (K=16=NQ).
#define FSLOT 73728u              // As 8KB (64x128B) + Bs 64KB (512x128B)
#define FSMEM 147456u
#define FNKT 32

__global__ void __launch_bounds__(512, 1) k_fused(
        const float* __restrict__ thf,
        const float* __restrict__ g2, const float* __restrict__ b2,
        float* __restrict__ dout, int l, int fin) {
    extern __shared__ char sm[];
    uint32_t sb = smem_u32(sm);
    const int tid = threadIdx.x;
    const int wid = tid >> 5, l5 = tid & 31;
    const int t0 = blockIdx.x * 64;
    const __half* W2L = g_w2h + (size_t)l*EE*FFN;
    const __half* W1L = g_w1h + (size_t)l*FFN*NQ;

    // ---- gen-role: m-tile = wid&3 (16 tokens), n8 pair base = (wid>>2)*2 ----
    const int gmt = wid & 3, gnt = (wid >> 2) * 2;
    const int gr = l5 >> 2, gc = l5 & 3;

    // qf A-fragment (static, fp16 m16n8k16 layout, K=16=NQ)
    uint32_t afrg[4];
    {
        float th[4];
        #pragma unroll
        for (int d = 0; d < 2; d++) {
            th[2*d]   = cosf(thf[l*NQ + 2*gc + 8*d]);
            th[2*d+1] = cosf(thf[l*NQ + 2*gc + 1 + 8*d]);
        }
        #pragma unroll
        for (int rr = 0; rr < 2; rr++) {      // token row r / r+8
            int tok = t0 + gmt*16 + gr + 8*rr;
            const float* hp = &g_h[(size_t)tok*EE];
            #pragma unroll
            for (int kk = 0; kk < 2; kk++) {  // k cols 2c / 2c+8
                float q0 = th[2*kk]   * cosf(hp[2*gc + 8*kk]);
                float q1 = th[2*kk+1] * cosf(hp[2*gc + 1 + 8*kk]);
                afrg[kk*2 + rr] = pack_h2(q0, q1);
            }
        }
    }

    // ---- main-role constants ----
    const int wm = (wid & 1) * 32, wn = (wid >> 1) * 64;
    const int lr = l5 & 7, lh = (l5 >> 3) & 1, lq = l5 >> 4;

    float c[2][8][4];
    #pragma unroll
    for (int mi = 0; mi < 2; mi++)
        #pragma unroll
        for (int ni = 0; ni < 8; ni++)
            #pragma unroll
            for (int r = 0; r < 4; r++) c[mi][ni][r] = 0.f;

    // B stage loader: 64KB = 4096 x 16B = 8 cp16/thread
    auto loadB = [&](int slot, int k0) {
        uint32_t bbs = sb + slot*FSLOT + 8192u;
        #pragma unroll
        for (int i = 0; i < 8; i++) {
            int idx = tid + i*512;
            int row = idx >> 3, qd = idx & 7;
            cp16(bbs + row*128 + ((qd ^ (row & 7)) << 4),
                 W2L + (size_t)row*FFN + k0 + qd*8);
        }
    };

    loadB(0, 0); CP_COMMIT();

    for (int s = 0; s < FNKT; s++) {
        CP_WAIT0();
        __syncthreads();
        if (s + 1 < FNKT) { loadB((s+1)&1, (s+1)*64); CP_COMMIT(); }

        // ---- generate A_s (64 tok x 64 hidden cols), fp16 into As slot ----
        uint32_t Asb = sb + (s&1)*FSLOT;
        #pragma unroll
        for (int jj = 0; jj < 2; jj++) {
            int nt = gnt + jj;                      // n8 tile 0..7
            int jglob = s*64 + nt*8 + gr;           // hidden col
            const uint32_t* wp = (const uint32_t*)(W1L + (size_t)jglob*NQ);
            uint32_t b0 = wp[gc], b1 = wp[gc + 4];
            float ga[4] = {0.f, 0.f, 0.f, 0.f};
            mma_f16(ga, afrg, b0, b1);
            #pragma unroll
            for (int r = 0; r < 4; r++) ga[r] = fmaxf(ga[r], 0.f);
            int row0 = gmt*16 + gr;
            uint32_t byte = (uint32_t)(nt*16 + 4*gc);
            uint32_t q = byte >> 4, off = byte & 15;
            uint32_t a0 = Asb + row0*128 + ((q ^ (row0 & 7)) << 4) + off;
            uint32_t a1 = Asb + (row0+8)*128 + ((q ^ ((row0+8) & 7)) << 4) + off;
            *(uint32_t*)(sm + (a0 - sb)) = pack_h2(ga[0], ga[1]);
            *(uint32_t*)(sm + (a1 - sb)) = pack_h2(ga[2], ga[3]);
        }
        __syncthreads();

        // ---- main mma: 32x64 warp tile over k=64 (4 k16 steps) ----
        uint32_t Bsb = Asb + 8192u;
        #pragma unroll
        for (int ks = 0; ks < 4; ks++) {
            uint32_t afr[2][4], bfr[4][4];
            #pragma unroll
            for (int mi = 0; mi < 2; mi++) {
                int row = wm + mi*16 + lr + lh*8;
                int q = 2*ks + lq;
                ldsm4(afr[mi], Asb + row*128 + ((q ^ (row & 7)) << 4));
            }
            #pragma unroll
            for (int g = 0; g < 4; g++) {
                int row = wn + g*16 + lr + lh*8;
                int q = 2*ks + lq;
                ldsm4(bfr[g], Bsb + row*128 + ((q ^ (row & 7)) << 4));
            }
            #pragma unroll
            for (int mi = 0; mi < 2; mi++)
                #pragma unroll
                for (int g = 0; g < 4; g++) {
                    mma_f16(c[mi][2*g],   afr[mi], bfr[g][0], bfr[g][2]);
                    mma_f16(c[mi][2*g+1], afr[mi], bfr[g][1], bfr[g][3]);
                }
        }
    }

    // ---- epilogue: stage accums to smem (stride 516 floats), then LN ----
    __syncthreads();
    float* ep = (float*)sm;
    #pragma unroll
    for (int mi = 0; mi < 2; mi++)
        #pragma unroll
        for (int ni = 0; ni < 8; ni++) {
            int row = wm + mi*16 + (l5 >> 2);
            int col = wn + ni*8 + (l5 & 3)*2;
            *(float2*)&ep[row*516 + col]     = make_float2(c[mi][ni][0], c[mi][ni][1]);
            *(float2*)&ep[(row+8)*516 + col] = make_float2(c[mi][ni][2], c[mi][ni][3]);
        }
    __syncthreads();

    float* outp = fin ? dout : g_h;
    int eb = l5 * 4;
    #pragma unroll
    for (int tt = 0; tt < 4; tt++) {
        int tl = wid*4 + tt;
        size_t t = t0 + tl;
        float v[16]; float s1 = 0.f, s2 = 0.f;
        #pragma unroll
        for (int j = 0; j < 4; j++) {
            float4 hv = *(const float4*)&g_h[t*EE + eb + j*128];
            float4 fv = *(const float4*)&ep[tl*516 + eb + j*128];
            v[j*4+0] = hv.x + fv.x; v[j*4+1] = hv.y + fv.y;
            v[j*4+2] = hv.z + fv.z; v[j*4+3] = hv.w + fv.w;
        }
        #pragma unroll
        for (int j = 0; j < 16; j++) { s1 += v[j]; s2 = fmaf(v[j], v[j], s2); }
        #pragma unroll
        for (int o = 16; o > 0; o >>= 1) {
            s1 += __shfl_xor_sync(0xffffffffu, s1, o);
            s2 += __shfl_xor_sync(0xffffffffu, s2, o);
        }
        float m  = s1 * (1.f/512.f);
        float var = fmaf(-m, m, s2 * (1.f/512.f));
        float rs = rsqrtf(var + 1e-5f);
        #pragma unroll
        for (int j = 0; j < 4; j++) {
            float4 gv = *(const float4*)&g2[l*EE + eb + j*128];
            float4 bv = *(const float4*)&b2[l*EE + eb + j*128];
            float4 o4;
            o4.x = (v[j*4+0]-m)*rs*gv.x + bv.x;
            o4.y = (v[j*4+1]-m)*rs*gv.y + bv.y;
            o4.z = (v[j*4+2]-m)*rs*gv.z + bv.z;
            o4.w = (v[j*4+3]-m)*rs*gv.w + bv.w;
            *(float4*)&outp[t*EE + eb + j*128] = o4;
        }
    }
}

// ---------------- launch ------------------------------------------------------
extern "C" void kernel_launch(void* const* d_in, const int* in_sizes, int n_in,
                              void* d_out, int out_size) {
    const float* x   = (const float*)d_in[0];
    const float* pe  = (const float*)d_in[1];
    const float* tha = (const float*)d_in[2];
    const float* thf = (const float*)d_in[3];
    const float* Wc  = (const float*)d_in[4];
    const float* W1  = (const float*)d_in[5];
    const float* W2  = (const float*)d_in[6];
    const float* g1  = (const float*)d_in[7];
    const float* b1  = (const float*)d_in[8];
    const float* g2  = (const float*)d_in[9];
    const float* b2  = (const float*)d_in[10];
    float* out = (float*)d_out;

    cudaFuncSetAttribute(k_fused, cudaFuncAttributeMaxDynamicSharedMemorySize, FSMEM);

    k_addpe<<<TT*EE/4/256, 256>>>(x, pe);
    k_cvtw2<<<(NL*EE*FFN/4)/256, 256>>>(W2);
    k_cvtw1<<<(NL*FFN*NQ/4)/256, 256>>>(W1);
    for (int l = 0; l < NL; l++) {
        k_attn<<<dim3(4, NH, BB), 512>>>(tha, l);
        k_comb_ln<<<TT/32, 256>>>(Wc, g1, b1, l);
        k_fused<<<TT/64, 512, FSMEM>>>(thf, g2, b2, out, l, (l == NL-1) ? 1 : 0);
    }
}

// round 15
// speedup vs baseline: 1.0012x; 1.0012x over previous
#include <cuda_runtime.h>
#include <cuda_fp16.h>
#include <math.h>
#include <stdint.h>

#define BB 8
#define SS 1024
#define EE 512
#define NH 8
#define NQ 16
#define FFN 2048
#define NL 4
#define TT (BB*SS)   // 8192 tokens

// ---------------- scratch (static device globals; no allocation) -------------
__device__ float g_h[TT*EE];                 // 16 MB  current hidden state
__device__ float g_attn[TT*NQ];              // 0.5 MB attention output
__device__ __half g_w2h[(size_t)NL*EE*FFN];  // 8 MB   W2 in fp16
__device__ __half g_w1h[(size_t)NL*FFN*NQ];  // 256 KB W1 in fp16

// ---------------- PTX helpers -------------------------------------------------
__device__ __forceinline__ float ex2f(float x) {
    float r; asm("ex2.approx.f32 %0, %1;" : "=f"(r) : "f"(x)); return r;
}
__device__ __forceinline__ uint32_t smem_u32(const void* p) {
    uint32_t a;
    asm("{ .reg .u64 t; cvta.to.shared.u64 t, %1; cvt.u32.u64 %0, t; }" : "=r"(a) : "l"(p));
    return a;
}
__device__ __forceinline__ uint32_t pack_h2(float a, float b) {
    __half2 h = __floats2half2_rn(a, b);
    return *(uint32_t*)&h;
}
__device__ __forceinline__ void cp16(uint32_t dst, const void* src) {
    asm volatile("cp.async.cg.shared.global [%0], [%1], 16;" :: "r"(dst), "l"(src) : "memory");
}
#define CP_COMMIT() asm volatile("cp.async.commit_group;" ::: "memory")
#define CP_WAIT0()  asm volatile("cp.async.wait_group 0;" ::: "memory")

__device__ __forceinline__ void ldsm4(uint32_t* r, uint32_t a) {
    asm volatile("ldmatrix.sync.aligned.m8n8.x4.shared.b16 {%0,%1,%2,%3}, [%4];"
                 : "=r"(r[0]), "=r"(r[1]), "=r"(r[2]), "=r"(r[3]) : "r"(a));
}
// fp16 mma, fp32 accumulate
__device__ __forceinline__ void mma_f16(float* c, const uint32_t* a, uint32_t b0, uint32_t b1) {
    asm volatile("mma.sync.aligned.m16n8k16.row.col.f32.f16.f16.f32 "
                 "{%0,%1,%2,%3}, {%4,%5,%6,%7}, {%8,%9}, {%0,%1,%2,%3};"
                 : "+f"(c[0]), "+f"(c[1]), "+f"(c[2]), "+f"(c[3])
                 : "r"(a[0]), "r"(a[1]), "r"(a[2]), "r"(a[3]), "r"(b0), "r"(b1));
}

// ---------------- K0: h = x + pe ---------------------------------------------
__global__ void k_addpe(const float* __restrict__ x, const float* __restrict__ pe) {
    int i = blockIdx.x * 256 + threadIdx.x;
    float4 xv = ((const float4*)x)[i];
    float4 pv = ((const float4*)pe)[i % (SS*EE/4)];
    float4 o; o.x = xv.x+pv.x; o.y = xv.y+pv.y; o.z = xv.z+pv.z; o.w = xv.w+pv.w;
    ((float4*)g_h)[i] = o;
}

// ---------------- Kcvt: W2/W1 -> fp16 copies ---------------------------------
__global__ void k_cvtw2(const float* __restrict__ w2) {
    size_t i = (size_t)blockIdx.x * 256 + threadIdx.x;
    float4 v = ((const float4*)w2)[i];
    ((uint32_t*)g_w2h)[2*i]   = pack_h2(v.x, v.y);
    ((uint32_t*)g_w2h)[2*i+1] = pack_h2(v.z, v.w);
}
__global__ void k_cvtw1(const float* __restrict__ w1) {
    size_t i = (size_t)blockIdx.x * 256 + threadIdx.x;
    float4 v = ((const float4*)w1)[i];
    ((uint32_t*)g_w1h)[2*i]   = pack_h2(v.x, v.y);
    ((uint32_t*)g_w1h)[2*i+1] = pack_h2(v.z, v.w);
}

// ---------------- KA: quantum attention, 2-way key split ---------------------
// block 512 thr: 256 queries x 2 key-halves. grid (4, NH, BB).
__global__ void __launch_bounds__(512) k_attn(const float* __restrict__ theta, int l) {
    __shared__ float2 sk[SS];
    __shared__ float4 pp[256];
    int b = blockIdx.z, hh = blockIdx.y, qc = blockIdx.x;
    float ct0 = cosf(theta[l*NQ + 2*hh]);
    float ct1 = cosf(theta[l*NQ + 2*hh + 1]);
    for (int k = threadIdx.x; k < SS; k += 512) {
        const float* hp = &g_h[((size_t)b*SS + k)*EE + 2*hh];
        sk[k] = make_float2(ct0 * cosf(hp[0]), ct1 * cosf(hp[1]));
    }
    __syncthreads();
    int qi = threadIdx.x & 255;
    int half = threadIdx.x >> 8;
    int q = qc*256 + qi;
    float2 qv = sk[q];
    const float SC = 0.7071067811865476f * 1.4426950408889634f;
    float qm0 = qv.x * SC, qm1 = qv.y * SC;
    float sum = 0.f, a0 = 0.f, a1 = 0.f;
    int k0 = half * 512;
    #pragma unroll 4
    for (int k = k0; k < k0 + 512; k++) {
        float2 kv = sk[k];
        float f = fmaf(qm0, kv.x, qm1 * kv.y);
        float e = ex2f(f);
        sum += e;
        a0 = fmaf(e, kv.x, a0);
        a1 = fmaf(e, kv.y, a1);
    }
    if (half == 1) pp[qi] = make_float4(sum, a0, a1, 0.f);
    __syncthreads();
    if (half == 0) {
        float4 o = pp[qi];
        sum += o.x; a0 += o.y; a1 += o.z;
        float inv = __frcp_rn(sum);
        float* op = &g_attn[((size_t)b*SS + q)*NQ + 2*hh];
        op[0] = a0 * inv;
        op[1] = a1 * inv;
    }
}

// ---------------- KB: attn @ Wc^T + residual + LN1 (warp-per-token) ----------
__global__ void __launch_bounds__(256) k_comb_ln(const float* __restrict__ Wc,
                          const float* __restrict__ g1, const float* __restrict__ b1,
                          int l) {
    __shared__ __align__(16) float wcs[NQ*EE];
    __shared__ float sat[32*NQ];
    int t0 = blockIdx.x * 32;
    const float* W = Wc + (size_t)l*EE*NQ;
    for (int idx = threadIdx.x; idx < EE*NQ; idx += 256) {
        int e = idx >> 4, i = idx & 15;
        wcs[i*EE + e] = W[idx];
    }
    for (int idx = threadIdx.x; idx < 32*NQ; idx += 256)
        sat[idx] = g_attn[(size_t)t0*NQ + idx];
    __syncthreads();

    int w = threadIdx.x >> 5, ln = threadIdx.x & 31;
    int eb = ln * 4;
    for (int tt = 0; tt < 4; tt++) {
        int tl = w*4 + tt;
        size_t t = t0 + tl;
        float v[16];
        #pragma unroll
        for (int j = 0; j < 4; j++) {
            float4 hv = *(const float4*)&g_h[t*EE + eb + j*128];
            v[j*4+0] = hv.x; v[j*4+1] = hv.y; v[j*4+2] = hv.z; v[j*4+3] = hv.w;
        }
        #pragma unroll
        for (int i = 0; i < NQ; i++) {
            float ai = sat[tl*NQ + i];
            const float4* wp = (const float4*)&wcs[i*EE + eb];
            #pragma unroll
            for (int j = 0; j < 4; j++) {
                float4 wv = wp[32*j];
                v[j*4+0] = fmaf(ai, wv.x, v[j*4+0]);
                v[j*4+1] = fmaf(ai, wv.y, v[j*4+1]);
                v[j*4+2] = fmaf(ai, wv.z, v[j*4+2]);
                v[j*4+3] = fmaf(ai, wv.w, v[j*4+3]);
            }
        }
        float s1 = 0.f, s2 = 0.f;
        #pragma unroll
        for (int j = 0; j < 16; j++) { s1 += v[j]; s2 = fmaf(v[j], v[j], s2); }
        #pragma unroll
        for (int o = 16; o > 0; o >>= 1) {
            s1 += __shfl_xor_sync(0xffffffffu, s1, o);
            s2 += __shfl_xor_sync(0xffffffffu, s2, o);
        }
        float m  = s1 * (1.f/512.f);
        float var = fmaf(-m, m, s2 * (1.f/512.f));
        float rs = rsqrtf(var + 1e-5f);
        #pragma unroll
        for (int j = 0; j < 4; j++) {
            float4 gv = *(const float4*)&g1[l*EE + eb + j*128];
            float4 bv = *(const float4*)&b1[l*EE + eb + j*128];
            float4 o4;
            o4.x = (v[j*4+0]-m)*rs*gv.x + bv.x;
            o4.y = (v[j*4+1]-m)*rs*gv.y + bv.y;
            o4.z = (v[j*4+2]-m)*rs*gv.z + bv.z;
            o4.w = (v[j*4+3]-m)*rs*gv.w + bv.w;
            *(float4*)&g_h[t*EE + eb + j*128] = o4;
        }
    }
}

// ---------------- KF: fused FFN (fp16 mma): relu(qf@W1^T)@W2^T + res + LN2 ---
// CTA: M=64 tokens x N=512 (full E). K-tile 64 halfs (128B rows), 32 stages,
// 2-stage cp.async. 512 threads = 16 warps; main warp tile 32x64.
// A tile generated per stage: 1 fp16 gen-mma per (16tok x 8col) tile (K=16=NQ).
#define FSLOT 73728u              // As 8KB (64x128B) + Bs 64KB (512x128B)
#define FSMEM 147456u
#define FNKT 32

__global__ void __launch_bounds__(512, 1) k_fused(
        const float* __restrict__ thf,
        const float* __restrict__ g2, const float* __restrict__ b2,
        float* __restrict__ dout, int l, int fin) {
    extern __shared__ char sm[];
    uint32_t sb = smem_u32(sm);
    const int tid = threadIdx.x;
    const int wid = tid >> 5, l5 = tid & 31;
    const int t0 = blockIdx.x * 64;
    const __half* W2L = g_w2h + (size_t)l*EE*FFN;
    const __half* W1L = g_w1h + (size_t)l*FFN*NQ;

    // ---- gen-role: m-tile = wid&3 (16 tokens), n8 pair base = (wid>>2)*2 ----
    const int gmt = wid & 3, gnt = (wid >> 2) * 2;
    const int gr = l5 >> 2, gc = l5 & 3;

    // qf A-fragment (static, fp16 m16n8k16 layout, K=16=NQ)
    uint32_t afrg[4];
    {
        float th[4];
        #pragma unroll
        for (int d = 0; d < 2; d++) {
            th[2*d]   = cosf(thf[l*NQ + 2*gc + 8*d]);
            th[2*d+1] = cosf(thf[l*NQ + 2*gc + 1 + 8*d]);
        }
        #pragma unroll
        for (int rr = 0; rr < 2; rr++) {      // token row r / r+8
            int tok = t0 + gmt*16 + gr + 8*rr;
            const float* hp = &g_h[(size_t)tok*EE];
            #pragma unroll
            for (int kk = 0; kk < 2; kk++) {  // k cols 2c / 2c+8
                float q0 = th[2*kk]   * cosf(hp[2*gc + 8*kk]);
                float q1 = th[2*kk+1] * cosf(hp[2*gc + 1 + 8*kk]);
                afrg[kk*2 + rr] = pack_h2(q0, q1);
            }
        }
    }

    // ---- main-role constants ----
    const int wm = (wid & 1) * 32, wn = (wid >> 1) * 64;
    const int lr = l5 & 7, lh = (l5 >> 3) & 1, lq = l5 >> 4;

    float c[2][8][4];
    #pragma unroll
    for (int mi = 0; mi < 2; mi++)
        #pragma unroll
        for (int ni = 0; ni < 8; ni++)
            #pragma unroll
            for (int r = 0; r < 4; r++) c[mi][ni][r] = 0.f;

    // B stage loader: 64KB = 4096 x 16B = 8 cp16/thread
    auto loadB = [&](int slot, int k0) {
        uint32_t bbs = sb + slot*FSLOT + 8192u;
        #pragma unroll
        for (int i = 0; i < 8; i++) {
            int idx = tid + i*512;
            int row = idx >> 3, qd = idx & 7;
            cp16(bbs + row*128 + ((qd ^ (row & 7)) << 4),
                 W2L + (size_t)row*FFN + k0 + qd*8);
        }
    };

    loadB(0, 0); CP_COMMIT();

    for (int s = 0; s < FNKT; s++) {
        CP_WAIT0();
        __syncthreads();
        if (s + 1 < FNKT) { loadB((s+1)&1, (s+1)*64); CP_COMMIT(); }

        // ---- generate A_s (64 tok x 64 hidden cols), fp16 into As slot ----
        uint32_t Asb = sb + (s&1)*FSLOT;
        #pragma unroll
        for (int jj = 0; jj < 2; jj++) {
            int nt = gnt + jj;                      // n8 tile 0..7
            int jglob = s*64 + nt*8 + gr;           // hidden col
            const uint32_t* wp = (const uint32_t*)(W1L + (size_t)jglob*NQ);
            uint32_t b0 = wp[gc], b1 = wp[gc + 4];
            float ga[4] = {0.f, 0.f, 0.f, 0.f};
            mma_f16(ga, afrg, b0, b1);
            #pragma unroll
            for (int r = 0; r < 4; r++) ga[r] = fmaxf(ga[r], 0.f);
            int row0 = gmt*16 + gr;
            uint32_t byte = (uint32_t)(nt*16 + 4*gc);
            uint32_t q = byte >> 4, off = byte & 15;
            uint32_t a0 = Asb + row0*128 + ((q ^ (row0 & 7)) << 4) + off;
            uint32_t a1 = Asb + (row0+8)*128 + ((q ^ ((row0+8) & 7)) << 4) + off;
            *(uint32_t*)(sm + (a0 - sb)) = pack_h2(ga[0], ga[1]);
            *(uint32_t*)(sm + (a1 - sb)) = pack_h2(ga[2], ga[3]);
        }
        __syncthreads();

        // ---- main mma: 32x64 warp tile over k=64 (4 k16 steps) ----
        uint32_t Bsb = Asb + 8192u;
        #pragma unroll
        for (int ks = 0; ks < 4; ks++) {
            uint32_t afr[2][4], bfr[4][4];
            #pragma unroll
            for (int mi = 0; mi < 2; mi++) {
                int row = wm + mi*16 + lr + lh*8;
                int q = 2*ks + lq;
                ldsm4(afr[mi], Asb + row*128 + ((q ^ (row & 7)) << 4));
            }
            #pragma unroll
            for (int g = 0; g < 4; g++) {
                int row = wn + g*16 + lr + lh*8;
                int q = 2*ks + lq;
                ldsm4(bfr[g], Bsb + row*128 + ((q ^ (row & 7)) << 4));
            }
            #pragma unroll
            for (int mi = 0; mi < 2; mi++)
                #pragma unroll
                for (int g = 0; g < 4; g++) {
                    mma_f16(c[mi][2*g],   afr[mi], bfr[g][0], bfr[g][2]);
                    mma_f16(c[mi][2*g+1], afr[mi], bfr[g][1], bfr[g][3]);
                }
        }
    }

    // ---- epilogue: stage accums to smem (stride 516 floats), then LN ----
    __syncthreads();
    float* ep = (float*)sm;
    #pragma unroll
    for (int mi = 0; mi < 2; mi++)
        #pragma unroll
        for (int ni = 0; ni < 8; ni++) {
            int row = wm + mi*16 + (l5 >> 2);
            int col = wn + ni*8 + (l5 & 3)*2;
            *(float2*)&ep[row*516 + col]     = make_float2(c[mi][ni][0], c[mi][ni][1]);
            *(float2*)&ep[(row+8)*516 + col] = make_float2(c[mi][ni][2], c[mi][ni][3]);
        }
    __syncthreads();

    float* outp = fin ? dout : g_h;
    int eb = l5 * 4;
    #pragma unroll
    for (int tt = 0; tt < 4; tt++) {
        int tl = wid*4 + tt;
        size_t t = t0 + tl;
        float v[16]; float s1 = 0.f, s2 = 0.f;
        #pragma unroll
        for (int j = 0; j < 4; j++) {
            float4 hv = *(const float4*)&g_h[t*EE + eb + j*128];
            float4 fv = *(const float4*)&ep[tl*516 + eb + j*128];
            v[j*4+0] = hv.x + fv.x; v[j*4+1] = hv.y + fv.y;
            v[j*4+2] = hv.z + fv.z; v[j*4+3] = hv.w + fv.w;
        }
        #pragma unroll
        for (int j = 0; j < 16; j++) { s1 += v[j]; s2 = fmaf(v[j], v[j], s2); }
        #pragma unroll
        for (int o = 16; o > 0; o >>= 1) {
            s1 += __shfl_xor_sync(0xffffffffu, s1, o);
            s2 += __shfl_xor_sync(0xffffffffu, s2, o);
        }
        float m  = s1 * (1.f/512.f);
        float var = fmaf(-m, m, s2 * (1.f/512.f));
        float rs = rsqrtf(var + 1e-5f);
        #pragma unroll
        for (int j = 0; j < 4; j++) {
            float4 gv = *(const float4*)&g2[l*EE + eb + j*128];
            float4 bv = *(const float4*)&b2[l*EE + eb + j*128];
            float4 o4;
            o4.x = (v[j*4+0]-m)*rs*gv.x + bv.x;
            o4.y = (v[j*4+1]-m)*rs*gv.y + bv.y;
            o4.z = (v[j*4+2]-m)*rs*gv.z + bv.z;
            o4.w = (v[j*4+3]-m)*rs*gv.w + bv.w;
            *(float4*)&outp[t*EE + eb + j*128] = o4;
        }
    }
}

// ---------------- launch ------------------------------------------------------
extern "C" void kernel_launch(void* const* d_in, const int* in_sizes, int n_in,
                              void* d_out, int out_size) {
    const float* x   = (const float*)d_in[0];
    const float* pe  = (const float*)d_in[1];
    const float* tha = (const float*)d_in[2];
    const float* thf = (const float*)d_in[3];
    const float* Wc  = (const float*)d_in[4];
    const float* W1  = (const float*)d_in[5];
    const float* W2  = (const float*)d_in[6];
    const float* g1  = (const float*)d_in[7];
    const float* b1  = (const float*)d_in[8];
    const float* g2  = (const float*)d_in[9];
    const float* b2  = (const float*)d_in[10];
    float* out = (float*)d_out;

    cudaFuncSetAttribute(k_fused, cudaFuncAttributeMaxDynamicSharedMemorySize, FSMEM);

    k_addpe<<<TT*EE/4/256, 256>>>(x, pe);
    k_cvtw2<<<(NL*EE*FFN/4)/256, 256>>>(W2);
    k_cvtw1<<<(NL*FFN*NQ/4)/256, 256>>>(W1);
    for (int l = 0; l < NL; l++) {
        k_attn<<<dim3(4, NH, BB), 512>>>(tha, l);
        k_comb_ln<<<TT/32, 256>>>(Wc, g1, b1, l);
        k_fused<<<TT/64, 512, FSMEM>>>(thf, g2, b2, out, l, (l == NL-1) ? 1 : 0);
    }
}

// round 16
// speedup vs baseline: 1.0020x; 1.0008x over previous
#include <cuda_runtime.h>
#include <cuda_fp16.h>
#include <math.h>
#include <stdint.h>

#define BB 8
#define SS 1024
#define EE 512
#define NH 8
#define NQ 16
#define FFN 2048
#define NL 4
#define TT (BB*SS)   // 8192 tokens

// ---------------- scratch (static device globals; no allocation) -------------
__device__ float g_h[TT*EE];                 // 16 MB  current hidden state
__device__ float g_attn[TT*NQ];              // 0.5 MB attention output
__device__ __half g_w2h[(size_t)NL*EE*FFN];  // 8 MB   W2 in fp16
__device__ __half g_w1h[(size_t)NL*FFN*NQ];  // 256 KB W1 in fp16

// ---------------- PTX helpers -------------------------------------------------
__device__ __forceinline__ float ex2f(float x) {
    float r; asm("ex2.approx.f32 %0, %1;" : "=f"(r) : "f"(x)); return r;
}
__device__ __forceinline__ uint32_t smem_u32(const void* p) {
    uint32_t a;
    asm("{ .reg .u64 t; cvta.to.shared.u64 t, %1; cvt.u32.u64 %0, t; }" : "=r"(a) : "l"(p));
    return a;
}
__device__ __forceinline__ uint32_t pack_h2(float a, float b) {
    __half2 h = __floats2half2_rn(a, b);
    return *(uint32_t*)&h;
}
__device__ __forceinline__ void cp16(uint32_t dst, const void* src) {
    asm volatile("cp.async.cg.shared.global [%0], [%1], 16;" :: "r"(dst), "l"(src) : "memory");
}
#define CP_COMMIT() asm volatile("cp.async.commit_group;" ::: "memory")
#define CP_WAIT0()  asm volatile("cp.async.wait_group 0;" ::: "memory")

__device__ __forceinline__ void ldsm4(uint32_t* r, uint32_t a) {
    asm volatile("ldmatrix.sync.aligned.m8n8.x4.shared.b16 {%0,%1,%2,%3}, [%4];"
                 : "=r"(r[0]), "=r"(r[1]), "=r"(r[2]), "=r"(r[3]) : "r"(a));
}
// fp16 mma, fp32 accumulate
__device__ __forceinline__ void mma_f16(float* c, const uint32_t* a, uint32_t b0, uint32_t b1) {
    asm volatile("mma.sync.aligned.m16n8k16.row.col.f32.f16.f16.f32 "
                 "{%0,%1,%2,%3}, {%4,%5,%6,%7}, {%8,%9}, {%0,%1,%2,%3};"
                 : "+f"(c[0]), "+f"(c[1]), "+f"(c[2]), "+f"(c[3])
                 : "r"(a[0]), "r"(a[1]), "r"(a[2]), "r"(a[3]), "r"(b0), "r"(b1));
}

// ---------------- K0: h = x + pe ---------------------------------------------
__global__ void k_addpe(const float* __restrict__ x, const float* __restrict__ pe) {
    int i = blockIdx.x * 256 + threadIdx.x;
    float4 xv = ((const float4*)x)[i];
    float4 pv = ((const float4*)pe)[i % (SS*EE/4)];
    float4 o; o.x = xv.x+pv.x; o.y = xv.y+pv.y; o.z = xv.z+pv.z; o.w = xv.w+pv.w;
    ((float4*)g_h)[i] = o;
}

// ---------------- Kcvt: W2/W1 -> fp16 copies ---------------------------------
__global__ void k_cvtw2(const float* __restrict__ w2) {
    size_t i = (size_t)blockIdx.x * 256 + threadIdx.x;
    float4 v = ((const float4*)w2)[i];
    ((uint32_t*)g_w2h)[2*i]   = pack_h2(v.x, v.y);
    ((uint32_t*)g_w2h)[2*i+1] = pack_h2(v.z, v.w);
}
__global__ void k_cvtw1(const float* __restrict__ w1) {
    size_t i = (size_t)blockIdx.x * 256 + threadIdx.x;
    float4 v = ((const float4*)w1)[i];
    ((uint32_t*)g_w1h)[2*i]   = pack_h2(v.x, v.y);
    ((uint32_t*)g_w1h)[2*i+1] = pack_h2(v.z, v.w);
}

// ---------------- KA: quantum attention, 2-way key split ---------------------
// block 512 thr: 256 queries x 2 key-halves. grid (4, NH, BB).
__global__ void __launch_bounds__(512) k_attn(const float* __restrict__ theta, int l) {
    __shared__ float2 sk[SS];
    __shared__ float4 pp[256];
    int b = blockIdx.z, hh = blockIdx.y, qc = blockIdx.x;
    float ct0 = cosf(theta[l*NQ + 2*hh]);
    float ct1 = cosf(theta[l*NQ + 2*hh + 1]);
    for (int k = threadIdx.x; k < SS; k += 512) {
        const float* hp = &g_h[((size_t)b*SS + k)*EE + 2*hh];
        sk[k] = make_float2(ct0 * cosf(hp[0]), ct1 * cosf(hp[1]));
    }
    __syncthreads();
    int qi = threadIdx.x & 255;
    int half = threadIdx.x >> 8;
    int q = qc*256 + qi;
    float2 qv = sk[q];
    const float SC = 0.7071067811865476f * 1.4426950408889634f;
    float qm0 = qv.x * SC, qm1 = qv.y * SC;
    float sum = 0.f, a0 = 0.f, a1 = 0.f;
    int k0 = half * 512;
    #pragma unroll 4
    for (int k = k0; k < k0 + 512; k++) {
        float2 kv = sk[k];
        float f = fmaf(qm0, kv.x, qm1 * kv.y);
        float e = ex2f(f);
        sum += e;
        a0 = fmaf(e, kv.x, a0);
        a1 = fmaf(e, kv.y, a1);
    }
    if (half == 1) pp[qi] = make_float4(sum, a0, a1, 0.f);
    __syncthreads();
    if (half == 0) {
        float4 o = pp[qi];
        sum += o.x; a0 += o.y; a1 += o.z;
        float inv = __frcp_rn(sum);
        float* op = &g_attn[((size_t)b*SS + q)*NQ + 2*hh];
        op[0] = a0 * inv;
        op[1] = a1 * inv;
    }
}

// ---------------- KB: attn @ Wc^T + residual + LN1 (warp-per-token) ----------
__global__ void __launch_bounds__(256) k_comb_ln(const float* __restrict__ Wc,
                          const float* __restrict__ g1, const float* __restrict__ b1,
                          int l) {
    __shared__ __align__(16) float wcs[NQ*EE];
    __shared__ float sat[32*NQ];
    int t0 = blockIdx.x * 32;
    const float* W = Wc + (size_t)l*EE*NQ;
    for (int idx = threadIdx.x; idx < EE*NQ; idx += 256) {
        int e = idx >> 4, i = idx & 15;
        wcs[i*EE + e] = W[idx];
    }
    for (int idx = threadIdx.x; idx < 32*NQ; idx += 256)
        sat[idx] = g_attn[(size_t)t0*NQ + idx];
    __syncthreads();

    int w = threadIdx.x >> 5, ln = threadIdx.x & 31;
    int eb = ln * 4;
    for (int tt = 0; tt < 4; tt++) {
        int tl = w*4 + tt;
        size_t t = t0 + tl;
        float v[16];
        #pragma unroll
        for (int j = 0; j < 4; j++) {
            float4 hv = *(const float4*)&g_h[t*EE + eb + j*128];
            v[j*4+0] = hv.x; v[j*4+1] = hv.y; v[j*4+2] = hv.z; v[j*4+3] = hv.w;
        }
        #pragma unroll
        for (int i = 0; i < NQ; i++) {
            float ai = sat[tl*NQ + i];
            const float4* wp = (const float4*)&wcs[i*EE + eb];
            #pragma unroll
            for (int j = 0; j < 4; j++) {
                float4 wv = wp[32*j];
                v[j*4+0] = fmaf(ai, wv.x, v[j*4+0]);
                v[j*4+1] = fmaf(ai, wv.y, v[j*4+1]);
                v[j*4+2] = fmaf(ai, wv.z, v[j*4+2]);
                v[j*4+3] = fmaf(ai, wv.w, v[j*4+3]);
            }
        }
        float s1 = 0.f, s2 = 0.f;
        #pragma unroll
        for (int j = 0; j < 16; j++) { s1 += v[j]; s2 = fmaf(v[j], v[j], s2); }
        #pragma unroll
        for (int o = 16; o > 0; o >>= 1) {
            s1 += __shfl_xor_sync(0xffffffffu, s1, o);
            s2 += __shfl_xor_sync(0xffffffffu, s2, o);
        }
        float m  = s1 * (1.f/512.f);
        float var = fmaf(-m, m, s2 * (1.f/512.f));
        float rs = rsqrtf(var + 1e-5f);
        #pragma unroll
        for (int j = 0; j < 4; j++) {
            float4 gv = *(const float4*)&g1[l*EE + eb + j*128];
            float4 bv = *(const float4*)&b1[l*EE + eb + j*128];
            float4 o4;
            o4.x = (v[j*4+0]-m)*rs*gv.x + bv.x;
            o4.y = (v[j*4+1]-m)*rs*gv.y + bv.y;
            o4.z = (v[j*4+2]-m)*rs*gv.z + bv.z;
            o4.w = (v[j*4+3]-m)*rs*gv.w + bv.w;
            *(float4*)&g_h[t*EE + eb + j*128] = o4;
        }
    }
}

// ---------------- KF: fused FFN (fp16 mma): relu(qf@W1^T)@W2^T + res + LN2 ---
// CTA: M=64 tokens x N=512 (full E). K-tile 64 halfs (128B rows), 32 stages,
// 2-stage cp.async. 512 threads = 16 warps; main warp tile 32x64.
// A tile generated per stage: 1 fp16 gen-mma per (16tok x 8col) tile (K=16=NQ).
#define FSLOT 73728u              // As 8KB (64x128B) + Bs 64KB (512x128B)
#define FSMEM 147456u
#define FNKT 32

__global__ void __launch_bounds__(512, 1) k_fused(
        const float* __restrict__ thf,
        const float* __restrict__ g2, const float* __restrict__ b2,
        float* __restrict__ dout, int l, int fin) {
    extern __shared__ char sm[];
    uint32_t sb = smem_u32(sm);
    const int tid = threadIdx.x;
    const int wid = tid >> 5, l5 = tid & 31;
    const int t0 = blockIdx.x * 64;
    const __half* W2L = g_w2h + (size_t)l*EE*FFN;
    const __half* W1L = g_w1h + (size_t)l*FFN*NQ;

    // ---- gen-role: m-tile = wid&3 (16 tokens), n8 pair base = (wid>>2)*2 ----
    const int gmt = wid & 3, gnt = (wid >> 2) * 2;
    const int gr = l5 >> 2, gc = l5 & 3;

    // qf A-fragment (static, fp16 m16n8k16 layout, K=16=NQ)
    uint32_t afrg[4];
    {
        float th[4];
        #pragma unroll
        for (int d = 0; d < 2; d++) {
            th[2*d]   = cosf(thf[l*NQ + 2*gc + 8*d]);
            th[2*d+1] = cosf(thf[l*NQ + 2*gc + 1 + 8*d]);
        }
        #pragma unroll
        for (int rr = 0; rr < 2; rr++) {      // token row r / r+8
            int tok = t0 + gmt*16 + gr + 8*rr;
            const float* hp = &g_h[(size_t)tok*EE];
            #pragma unroll
            for (int kk = 0; kk < 2; kk++) {  // k cols 2c / 2c+8
                float q0 = th[2*kk]   * cosf(hp[2*gc + 8*kk]);
                float q1 = th[2*kk+1] * cosf(hp[2*gc + 1 + 8*kk]);
                afrg[kk*2 + rr] = pack_h2(q0, q1);
            }
        }
    }

    // ---- main-role constants ----
    const int wm = (wid & 1) * 32, wn = (wid >> 1) * 64;
    const int lr = l5 & 7, lh = (l5 >> 3) & 1, lq = l5 >> 4;

    float c[2][8][4];
    #pragma unroll
    for (int mi = 0; mi < 2; mi++)
        #pragma unroll
        for (int ni = 0; ni < 8; ni++)
            #pragma unroll
            for (int r = 0; r < 4; r++) c[mi][ni][r] = 0.f;

    // B stage loader: 64KB = 4096 x 16B = 8 cp16/thread
    auto loadB = [&](int slot, int k0) {
        uint32_t bbs = sb + slot*FSLOT + 8192u;
        #pragma unroll
        for (int i = 0; i < 8; i++) {
            int idx = tid + i*512;
            int row = idx >> 3, qd = idx & 7;
            cp16(bbs + row*128 + ((qd ^ (row & 7)) << 4),
                 W2L + (size_t)row*FFN + k0 + qd*8);
        }
    };

    loadB(0, 0); CP_COMMIT();

    for (int s = 0; s < FNKT; s++) {
        CP_WAIT0();
        __syncthreads();
        if (s + 1 < FNKT) { loadB((s+1)&1, (s+1)*64); CP_COMMIT(); }

        // ---- generate A_s (64 tok x 64 hidden cols), fp16 into As slot ----
        uint32_t Asb = sb + (s&1)*FSLOT;
        #pragma unroll
        for (int jj = 0; jj < 2; jj++) {
            int nt = gnt + jj;                      // n8 tile 0..7
            int jglob = s*64 + nt*8 + gr;           // hidden col
            const uint32_t* wp = (const uint32_t*)(W1L + (size_t)jglob*NQ);
            uint32_t b0 = wp[gc], b1 = wp[gc + 4];
            float ga[4] = {0.f, 0.f, 0.f, 0.f};
            mma_f16(ga, afrg, b0, b1);
            #pragma unroll
            for (int r = 0; r < 4; r++) ga[r] = fmaxf(ga[r], 0.f);
            int row0 = gmt*16 + gr;
            uint32_t byte = (uint32_t)(nt*16 + 4*gc);
            uint32_t q = byte >> 4, off = byte & 15;
            uint32_t a0 = Asb + row0*128 + ((q ^ (row0 & 7)) << 4) + off;
            uint32_t a1 = Asb + (row0+8)*128 + ((q ^ ((row0+8) & 7)) << 4) + off;
            *(uint32_t*)(sm + (a0 - sb)) = pack_h2(ga[0], ga[1]);
            *(uint32_t*)(sm + (a1 - sb)) = pack_h2(ga[2], ga[3]);
        }
        __syncthreads();

        // ---- main mma: 32x64 warp tile over k=64 (4 k16 steps) ----
        uint32_t Bsb = Asb + 8192u;
        #pragma unroll
        for (int ks = 0; ks < 4; ks++) {
            uint32_t afr[2][4], bfr[4][4];
            #pragma unroll
            for (int mi = 0; mi < 2; mi++) {
                int row = wm + mi*16 + lr + lh*8;
                int q = 2*ks + lq;
                ldsm4(afr[mi], Asb + row*128 + ((q ^ (row & 7)) << 4));
            }
            #pragma unroll
            for (int g = 0; g < 4; g++) {
                int row = wn + g*16 + lr + lh*8;
                int q = 2*ks + lq;
                ldsm4(bfr[g], Bsb + row*128 + ((q ^ (row & 7)) << 4));
            }
            #pragma unroll
            for (int mi = 0; mi < 2; mi++)
                #pragma unroll
                for (int g = 0; g < 4; g++) {
                    mma_f16(c[mi][2*g],   afr[mi], bfr[g][0], bfr[g][2]);
                    mma_f16(c[mi][2*g+1], afr[mi], bfr[g][1], bfr[g][3]);
                }
        }
    }

    // ---- epilogue: stage accums to smem (stride 516 floats), then LN ----
    __syncthreads();
    float* ep = (float*)sm;
    #pragma unroll
    for (int mi = 0; mi < 2; mi++)
        #pragma unroll
        for (int ni = 0; ni < 8; ni++) {
            int row = wm + mi*16 + (l5 >> 2);
            int col = wn + ni*8 + (l5 & 3)*2;
            *(float2*)&ep[row*516 + col]     = make_float2(c[mi][ni][0], c[mi][ni][1]);
            *(float2*)&ep[(row+8)*516 + col] = make_float2(c[mi][ni][2], c[mi][ni][3]);
        }
    __syncthreads();

    float* outp = fin ? dout : g_h;
    int eb = l5 * 4;
    #pragma unroll
    for (int tt = 0; tt < 4; tt++) {
        int tl = wid*4 + tt;
        size_t t = t0 + tl;
        float v[16]; float s1 = 0.f, s2 = 0.f;
        #pragma unroll
        for (int j = 0; j < 4; j++) {
            float4 hv = *(const float4*)&g_h[t*EE + eb + j*128];
            float4 fv = *(const float4*)&ep[tl*516 + eb + j*128];
            v[j*4+0] = hv.x + fv.x; v[j*4+1] = hv.y + fv.y;
            v[j*4+2] = hv.z + fv.z; v[j*4+3] = hv.w + fv.w;
        }
        #pragma unroll
        for (int j = 0; j < 16; j++) { s1 += v[j]; s2 = fmaf(v[j], v[j], s2); }
        #pragma unroll
        for (int o = 16; o > 0; o >>= 1) {
            s1 += __shfl_xor_sync(0xffffffffu, s1, o);
            s2 += __shfl_xor_sync(0xffffffffu, s2, o);
        }
        float m  = s1 * (1.f/512.f);
        float var = fmaf(-m, m, s2 * (1.f/512.f));
        float rs = rsqrtf(var + 1e-5f);
        #pragma unroll
        for (int j = 0; j < 4; j++) {
            float4 gv = *(const float4*)&g2[l*EE + eb + j*128];
            float4 bv = *(const float4*)&b2[l*EE + eb + j*128];
            float4 o4;
            o4.x = (v[j*4+0]-m)*rs*gv.x + bv.x;
            o4.y = (v[j*4+1]-m)*rs*gv.y + bv.y;
            o4.z = (v[j*4+2]-m)*rs*gv.z + bv.z;
            o4.w = (v[j*4+3]-m)*rs*gv.w + bv.w;
            *(float4*)&outp[t*EE + eb + j*128] = o4;
        }
    }
}

// ---------------- launch ------------------------------------------------------
extern "C" void kernel_launch(void* const* d_in, const int* in_sizes, int n_in,
                              void* d_out, int out_size) {
    const float* x   = (const float*)d_in[0];
    const float* pe  = (const float*)d_in[1];
    const float* tha = (const float*)d_in[2];
    const float* thf = (const float*)d_in[3];
    const float* Wc  = (const float*)d_in[4];
    const float* W1  = (const float*)d_in[5];
    const float* W2  = (const float*)d_in[6];
    const float* g1  = (const float*)d_in[7];
    const float* b1  = (const float*)d_in[8];
    const float* g2  = (const float*)d_in[9];
    const float* b2  = (const float*)d_in[10];
    float* out = (float*)d_out;

    cudaFuncSetAttribute(k_fused, cudaFuncAttributeMaxDynamicSharedMemorySize, FSMEM);

    k_addpe<<<TT*EE/4/256, 256>>>(x, pe);
    k_cvtw2<<<(NL*EE*FFN/4)/256, 256>>>(W2);
    k_cvtw1<<<(NL*FFN*NQ/4)/256, 256>>>(W1);
    for (int l = 0; l < NL; l++) {
        k_attn<<<dim3(4, NH, BB), 512>>>(tha, l);
        k_comb_ln<<<TT/32, 256>>>(Wc, g1, b1, l);
        k_fused<<<TT/64, 512, FSMEM>>>(thf, g2, b2, out, l, (l == NL-1) ? 1 : 0);
    }
}